// round 15
// baseline (speedup 1.0000x reference)
#include <cuda_runtime.h>

#define BATCH 16
#define TLEN  512
#define DIMSZ 384
#define DMAX  4096
#define MAIN  (BATCH * DIMSZ * DMAX)   // 25,165,824 floats
#define ROWS  4                        // d-rows per block
#define MAXMEL 3584                    // duration < 8 -> mel <= 7*512 = 3584
#define GSLOTS (MAXMEL / 4)            // 896 gather float4 slots per row

// ---------------------------------------------------------------------------
// Fused kernel: grid (96, 16) = 1536 blocks x 256 threads, stcs stores.
// R15 = R12 gather body + per-warp LOOP SPLIT on the pad boundary:
// the pad condition is monotonic in s, so each warp computes one cut point
// and runs two straight-line loops (gather / zero-store) with no per-
// iteration branch, no BSSY reconvergence, no divergence.
//  * phase 0: frames [3584,4096) are provably pad -> zero stores at entry
//  * s <  s_cut: gather with per-element (frame<mel) select (R12 body)
//  * s >= s_cut: dependency-free zero stores
// ---------------------------------------------------------------------------
__global__ void __launch_bounds__(256, 8) length_regulator_kernel(
    const float* __restrict__ x, const int* __restrict__ dur,
    float* __restrict__ out, int out_size)
{
    const int b   = blockIdx.y;
    const int dg  = blockIdx.x;          // 0..95
    const int tid = threadIdx.x;         // 0..255
    const int d0  = dg * ROWS;

    __shared__ short s_idx[MAXMEL];      // 7 KB, NOT initialized (masked reads)
    __shared__ float s_x[ROWS * TLEN];   // 8 KB
    __shared__ int   wsum[8], woff[8];

    float* ob = out + ((size_t)b * DIMSZ + d0) * DMAX;

    // ---- phase 0: unconditional-pad zero stores, issued before anything ----
    {
        const float4 z = make_float4(0.f, 0.f, 0.f, 0.f);
        const int zslot = GSLOTS + (tid & 127);       // 896..1023
        const int rbase = tid >> 7;                   // 0 or 1
        __stcs(reinterpret_cast<float4*>(ob + (size_t)rbase * DMAX) + zslot, z);
        __stcs(reinterpret_cast<float4*>(ob + (size_t)(rbase + 2) * DMAX) + zslot, z);
    }

    // ---- stage x rows (512 float4, 2/thread, coalesced) ----
    const float4* xb4 = reinterpret_cast<const float4*>(
        x + ((size_t)b * DIMSZ + d0) * TLEN);
    reinterpret_cast<float4*>(s_x)[tid]       = xb4[tid];
    reinterpret_cast<float4*>(s_x)[tid + 256] = xb4[tid + 256];

    // ---- scan 512 durations with 256 threads (2 adjacent steps/thread) ----
    const int2 dd = reinterpret_cast<const int2*>(dur + b * TLEN)[tid];
    int da = dd.x, db = dd.y;
    const int lane = tid & 31;
    const int wid  = tid >> 5;           // 0..7

    int v = da + db;                     // pair sum
    const int pair = v;
    #pragma unroll
    for (int o = 1; o < 32; o <<= 1) {
        int n = __shfl_up_sync(0xffffffffu, v, o);
        if (lane >= o) v += n;
    }
    if (lane == 31) wsum[wid] = v;
    __syncthreads();
    if (tid < 8) {
        int w = wsum[tid];
        #pragma unroll
        for (int o = 1; o < 8; o <<= 1) {
            int n = __shfl_up_sync(0x000000ffu, w, o);
            if (tid >= o) w += n;
        }
        woff[tid] = w;
    }
    __syncthreads();

    const int total = woff[7];
    int c0, c1, mel;
    if (total == 0) {                    // all-zero row: duration := 1
        da = 1; db = 1;
        c0 = 2 * tid + 1;
        c1 = 2 * tid + 2;
        mel = TLEN;
    } else {
        const int excl = v - pair + (wid ? woff[wid - 1] : 0);
        c0 = excl + da;
        c1 = c0 + db;
        mel = total;
    }

    // ---- scatter timestep ids into smem idx (disjoint ranges, cover [0,mel))
    {
        const short t0 = (short)(2 * tid), t1 = (short)(2 * tid + 1);
        int s0 = c0 - da;
        for (int k = 0; k < da; k++) s_idx[s0 + k] = t0;
        int s1 = c1 - db;
        for (int k = 0; k < db; k++) s_idx[s1 + k] = t1;
    }
    __syncthreads();

    // ---- per-warp cut: first s whose whole warp range is padding ----
    // warp covers frames [(s*256 + wbase)*4, +128); pad iff start >= mel.
    const int wbase = tid & ~31;         // lane-uniform
    // smallest s with (s*256 + wbase) >= ceil(mel/4):
    int s_cut = (((mel + 3) >> 2) - wbase + 255) >> 8;  // may be 0..4
    if (s_cut < 0) s_cut = 0;
    if (s_cut > 4) s_cut = 4;

    // ---- loop 1: gather region (straight-line, no branches) ----
    for (int s = 0; s < s_cut; s++) {
        const int slot = s * 256 + tid;              // < GSLOTS by construction
        const int fbase = slot * 4;
        const short4 iv = reinterpret_cast<const short4*>(s_idx)[slot];
        const int i0 = iv.x & 511, i1 = iv.y & 511;
        const int i2 = iv.z & 511, i3 = iv.w & 511;
        const bool v0 = fbase     < mel, v1 = fbase + 1 < mel;
        const bool v2 = fbase + 2 < mel, v3 = fbase + 3 < mel;
        #pragma unroll
        for (int r = 0; r < ROWS; r++) {
            const float* sx = s_x + r * TLEN;
            float4 val;
            val.x = v0 ? sx[i0] : 0.0f;
            val.y = v1 ? sx[i1] : 0.0f;
            val.z = v2 ? sx[i2] : 0.0f;
            val.w = v3 ? sx[i3] : 0.0f;
            __stcs(reinterpret_cast<float4*>(ob + (size_t)r * DMAX) + slot, val);
        }
    }

    // ---- loop 2: pad region (dependency-free zero stores) ----
    const float4 z = make_float4(0.f, 0.f, 0.f, 0.f);
    for (int s = s_cut; s < 4; s++) {
        const int slot = s * 256 + tid;
        if (slot < GSLOTS) {                         // warp-uniform guard
            #pragma unroll
            for (int r = 0; r < ROWS; r++)
                __stcs(reinterpret_cast<float4*>(ob + (size_t)r * DMAX) + slot, z);
        }
    }

    // ---- mel_len output + tail zeroing ----
    if (dg == 0) {
        if (tid == 0 && out_size >= MAIN + BATCH)
            out[MAIN + b] = (float)mel;
        if (b == 0) {
            for (int p = MAIN + BATCH + tid; p < out_size; p += 256)
                out[p] = 0.0f;
        }
    }
}

extern "C" void kernel_launch(void* const* d_in, const int* in_sizes, int n_in,
                              void* d_out, int out_size)
{
    const float* x   = (const float*)d_in[0];   // (16, 384, 512) f32
    const int*   dur = (const int*)d_in[1];     // (16, 512) i32
    float*       out = (float*)d_out;

    length_regulator_kernel<<<dim3(DIMSZ / ROWS, BATCH), 256>>>(x, dur, out, out_size);
}

// round 16
// speedup vs baseline: 1.0031x; 1.0031x over previous
#include <cuda_runtime.h>

#define BATCH 16
#define TLEN  512
#define DIMSZ 384
#define DMAX  4096
#define MAIN  (BATCH * DIMSZ * DMAX)   // 25,165,824 floats
#define ROWS  4                        // d-rows per block
#define MAXMEL 3584                    // duration < 8 -> mel <= 7*512 = 3584
#define GSLOTS (MAXMEL / 4)            // 896 gather float4 slots per row

// ---------------------------------------------------------------------------
// Fused kernel: grid (96, 16) = 1536 blocks x 256 threads, stcs stores.
// R16 = R15 with the dur load hoisted to the first instruction (its DRAM
// latency overlaps phase-0 zero stores + x staging instead of sitting on the
// scan's critical path). Structure:
//  * phase 0: frames [3584,4096) are provably pad -> zero stores at entry
//  * per-warp loop split on the monotonic pad boundary (no branches, no BSSY)
//  * s <  s_cut: straight-line gather, per-element (frame<mel) select
//  * s >= s_cut: dependency-free zero stores
// Wall time is pinned at the ~20.5us DRAM write-drain floor for the 100.7 MB
// output; this kernel sits comfortably under it.
// ---------------------------------------------------------------------------
__global__ void __launch_bounds__(256, 8) length_regulator_kernel(
    const float* __restrict__ x, const int* __restrict__ dur,
    float* __restrict__ out, int out_size)
{
    const int b   = blockIdx.y;
    const int dg  = blockIdx.x;          // 0..95
    const int tid = threadIdx.x;         // 0..255
    const int d0  = dg * ROWS;

    // issue the scan input load FIRST: its latency hides under phase 0 + staging
    const int2 dd = reinterpret_cast<const int2*>(dur + b * TLEN)[tid];

    __shared__ short s_idx[MAXMEL];      // 7 KB, NOT initialized (masked reads)
    __shared__ float s_x[ROWS * TLEN];   // 8 KB
    __shared__ int   wsum[8], woff[8];

    float* ob = out + ((size_t)b * DIMSZ + d0) * DMAX;

    // ---- phase 0: unconditional-pad zero stores ----
    {
        const float4 z = make_float4(0.f, 0.f, 0.f, 0.f);
        const int zslot = GSLOTS + (tid & 127);       // 896..1023
        const int rbase = tid >> 7;                   // 0 or 1
        __stcs(reinterpret_cast<float4*>(ob + (size_t)rbase * DMAX) + zslot, z);
        __stcs(reinterpret_cast<float4*>(ob + (size_t)(rbase + 2) * DMAX) + zslot, z);
    }

    // ---- stage x rows (512 float4, 2/thread, coalesced) ----
    const float4* xb4 = reinterpret_cast<const float4*>(
        x + ((size_t)b * DIMSZ + d0) * TLEN);
    reinterpret_cast<float4*>(s_x)[tid]       = xb4[tid];
    reinterpret_cast<float4*>(s_x)[tid + 256] = xb4[tid + 256];

    // ---- scan 512 durations with 256 threads (2 adjacent steps/thread) ----
    int da = dd.x, db = dd.y;
    const int lane = tid & 31;
    const int wid  = tid >> 5;           // 0..7

    int v = da + db;                     // pair sum
    const int pair = v;
    #pragma unroll
    for (int o = 1; o < 32; o <<= 1) {
        int n = __shfl_up_sync(0xffffffffu, v, o);
        if (lane >= o) v += n;
    }
    if (lane == 31) wsum[wid] = v;
    __syncthreads();
    if (tid < 8) {
        int w = wsum[tid];
        #pragma unroll
        for (int o = 1; o < 8; o <<= 1) {
            int n = __shfl_up_sync(0x000000ffu, w, o);
            if (tid >= o) w += n;
        }
        woff[tid] = w;
    }
    __syncthreads();

    const int total = woff[7];
    int c0, c1, mel;
    if (total == 0) {                    // all-zero row: duration := 1
        da = 1; db = 1;
        c0 = 2 * tid + 1;
        c1 = 2 * tid + 2;
        mel = TLEN;
    } else {
        const int excl = v - pair + (wid ? woff[wid - 1] : 0);
        c0 = excl + da;
        c1 = c0 + db;
        mel = total;
    }

    // ---- scatter timestep ids into smem idx (disjoint ranges, cover [0,mel))
    {
        const short t0 = (short)(2 * tid), t1 = (short)(2 * tid + 1);
        int s0 = c0 - da;
        for (int k = 0; k < da; k++) s_idx[s0 + k] = t0;
        int s1 = c1 - db;
        for (int k = 0; k < db; k++) s_idx[s1 + k] = t1;
    }
    __syncthreads();

    // ---- per-warp cut: first s whose whole warp range is padding ----
    // warp covers frames [(s*256 + wbase)*4, +128); pad iff start >= mel.
    const int wbase = tid & ~31;         // lane-uniform
    int s_cut = (((mel + 3) >> 2) - wbase + 255) >> 8;  // mel>=1 -> s_cut>=0
    if (s_cut > 4) s_cut = 4;

    // ---- loop 1: gather region (straight-line, no branches) ----
    for (int s = 0; s < s_cut; s++) {
        const int slot = s * 256 + tid;              // < GSLOTS by construction
        const int fbase = slot * 4;
        const short4 iv = reinterpret_cast<const short4*>(s_idx)[slot];
        const int i0 = iv.x & 511, i1 = iv.y & 511;
        const int i2 = iv.z & 511, i3 = iv.w & 511;
        const bool v0 = fbase     < mel, v1 = fbase + 1 < mel;
        const bool v2 = fbase + 2 < mel, v3 = fbase + 3 < mel;
        #pragma unroll
        for (int r = 0; r < ROWS; r++) {
            const float* sx = s_x + r * TLEN;
            float4 val;
            val.x = v0 ? sx[i0] : 0.0f;
            val.y = v1 ? sx[i1] : 0.0f;
            val.z = v2 ? sx[i2] : 0.0f;
            val.w = v3 ? sx[i3] : 0.0f;
            __stcs(reinterpret_cast<float4*>(ob + (size_t)r * DMAX) + slot, val);
        }
    }

    // ---- loop 2: pad region (dependency-free zero stores) ----
    const float4 z = make_float4(0.f, 0.f, 0.f, 0.f);
    for (int s = s_cut; s < 4; s++) {
        const int slot = s * 256 + tid;
        if (slot < GSLOTS) {                         // warp-uniform guard
            #pragma unroll
            for (int r = 0; r < ROWS; r++)
                __stcs(reinterpret_cast<float4*>(ob + (size_t)r * DMAX) + slot, z);
        }
    }

    // ---- mel_len output + tail zeroing ----
    if (dg == 0) {
        if (tid == 0 && out_size >= MAIN + BATCH)
            out[MAIN + b] = (float)mel;
        if (b == 0) {
            for (int p = MAIN + BATCH + tid; p < out_size; p += 256)
                out[p] = 0.0f;
        }
    }
}

extern "C" void kernel_launch(void* const* d_in, const int* in_sizes, int n_in,
                              void* d_out, int out_size)
{
    const float* x   = (const float*)d_in[0];   // (16, 384, 512) f32
    const int*   dur = (const int*)d_in[1];     // (16, 512) i32
    float*       out = (float*)d_out;

    length_regulator_kernel<<<dim3(DIMSZ / ROWS, BATCH), 256>>>(x, dur, out, out_size);
}

// round 17
// speedup vs baseline: 1.0094x; 1.0063x over previous
#include <cuda_runtime.h>

#define BATCH 16
#define TLEN  512
#define DIMSZ 384
#define DMAX  4096
#define MAIN  (BATCH * DIMSZ * DMAX)   // 25,165,824 floats
#define ROWS  4                        // d-rows per block
#define MAXMEL 3584                    // duration < 8 -> mel <= 7*512 = 3584
#define GSLOTS (MAXMEL / 4)            // 896 gather float4 slots per row

// ---------------------------------------------------------------------------
// Fused kernel: grid (96, 16) = 1536 blocks x 256 threads, stcs stores.
// R17 = R16 with the last predicated branch removed from the store stream:
// loop 2's slot guard becomes a per-warp uniform trip count (s_max).
// Structure:
//  * dur load issued first (latency hides under phase 0 + x staging)
//  * phase 0: frames [3584,4096) are provably pad -> zero stores at entry
//  * per-warp loop split on the monotonic pad boundary (no branches, no BSSY)
//  * s in [0, s_cut): straight-line gather, per-element (frame<mel) select
//  * s in [s_cut, s_max): dependency-free zero stores
// Wall time sits on the ~20.5us DRAM write-drain floor for the 100.7 MB
// output; the kernel is comfortably under it.
// ---------------------------------------------------------------------------
__global__ void __launch_bounds__(256, 8) length_regulator_kernel(
    const float* __restrict__ x, const int* __restrict__ dur,
    float* __restrict__ out, int out_size)
{
    const int b   = blockIdx.y;
    const int dg  = blockIdx.x;          // 0..95
    const int tid = threadIdx.x;         // 0..255
    const int d0  = dg * ROWS;

    // issue the scan input load FIRST: latency hides under phase 0 + staging
    const int2 dd = reinterpret_cast<const int2*>(dur + b * TLEN)[tid];

    __shared__ short s_idx[MAXMEL];      // 7 KB, NOT initialized (masked reads)
    __shared__ float s_x[ROWS * TLEN];   // 8 KB
    __shared__ int   wsum[8], woff[8];

    float* ob = out + ((size_t)b * DIMSZ + d0) * DMAX;

    // ---- phase 0: unconditional-pad zero stores ----
    {
        const float4 z = make_float4(0.f, 0.f, 0.f, 0.f);
        const int zslot = GSLOTS + (tid & 127);       // 896..1023
        const int rbase = tid >> 7;                   // 0 or 1
        __stcs(reinterpret_cast<float4*>(ob + (size_t)rbase * DMAX) + zslot, z);
        __stcs(reinterpret_cast<float4*>(ob + (size_t)(rbase + 2) * DMAX) + zslot, z);
    }

    // ---- stage x rows (512 float4, 2/thread, coalesced) ----
    const float4* xb4 = reinterpret_cast<const float4*>(
        x + ((size_t)b * DIMSZ + d0) * TLEN);
    reinterpret_cast<float4*>(s_x)[tid]       = xb4[tid];
    reinterpret_cast<float4*>(s_x)[tid + 256] = xb4[tid + 256];

    // ---- scan 512 durations with 256 threads (2 adjacent steps/thread) ----
    int da = dd.x, db = dd.y;
    const int lane = tid & 31;
    const int wid  = tid >> 5;           // 0..7

    int v = da + db;                     // pair sum
    const int pair = v;
    #pragma unroll
    for (int o = 1; o < 32; o <<= 1) {
        int n = __shfl_up_sync(0xffffffffu, v, o);
        if (lane >= o) v += n;
    }
    if (lane == 31) wsum[wid] = v;
    __syncthreads();
    if (tid < 8) {
        int w = wsum[tid];
        #pragma unroll
        for (int o = 1; o < 8; o <<= 1) {
            int n = __shfl_up_sync(0x000000ffu, w, o);
            if (tid >= o) w += n;
        }
        woff[tid] = w;
    }
    __syncthreads();

    const int total = woff[7];
    int c0, c1, mel;
    if (total == 0) {                    // all-zero row: duration := 1
        da = 1; db = 1;
        c0 = 2 * tid + 1;
        c1 = 2 * tid + 2;
        mel = TLEN;
    } else {
        const int excl = v - pair + (wid ? woff[wid - 1] : 0);
        c0 = excl + da;
        c1 = c0 + db;
        mel = total;
    }

    // ---- scatter timestep ids into smem idx (disjoint ranges, cover [0,mel))
    {
        const short t0 = (short)(2 * tid), t1 = (short)(2 * tid + 1);
        int s0 = c0 - da;
        for (int k = 0; k < da; k++) s_idx[s0 + k] = t0;
        int s1 = c1 - db;
        for (int k = 0; k < db; k++) s_idx[s1 + k] = t1;
    }
    __syncthreads();

    // ---- per-warp bounds (all lane-uniform) ----
    // warp covers frames [(s*256 + wbase)*4, +128); pad iff start >= mel.
    const int wbase = tid & ~31;
    int s_cut = (((mel + 3) >> 2) - wbase + 255) >> 8;  // mel>=1 -> s_cut>=0
    if (s_cut > 4) s_cut = 4;
    // last valid slot for this warp is < GSLOTS: warps with wbase<128 reach
    // s=3 (slots 896..1023 excluded), others stop at s=3 too except low half.
    const int s_max = (wbase < (GSLOTS & 255)) ? 4 : (GSLOTS >> 8);  // 4 or 3

    // ---- loop 1: gather region (straight-line, no branches) ----
    for (int s = 0; s < s_cut; s++) {
        const int slot = s * 256 + tid;              // < GSLOTS by construction
        const int fbase = slot * 4;
        const short4 iv = reinterpret_cast<const short4*>(s_idx)[slot];
        const int i0 = iv.x & 511, i1 = iv.y & 511;
        const int i2 = iv.z & 511, i3 = iv.w & 511;
        const bool v0 = fbase     < mel, v1 = fbase + 1 < mel;
        const bool v2 = fbase + 2 < mel, v3 = fbase + 3 < mel;
        #pragma unroll
        for (int r = 0; r < ROWS; r++) {
            const float* sx = s_x + r * TLEN;
            float4 val;
            val.x = v0 ? sx[i0] : 0.0f;
            val.y = v1 ? sx[i1] : 0.0f;
            val.z = v2 ? sx[i2] : 0.0f;
            val.w = v3 ? sx[i3] : 0.0f;
            __stcs(reinterpret_cast<float4*>(ob + (size_t)r * DMAX) + slot, val);
        }
    }

    // ---- loop 2: pad region (dependency-free zero stores, no guard) ----
    const float4 z = make_float4(0.f, 0.f, 0.f, 0.f);
    for (int s = s_cut; s < s_max; s++) {
        const int slot = s * 256 + tid;
        #pragma unroll
        for (int r = 0; r < ROWS; r++)
            __stcs(reinterpret_cast<float4*>(ob + (size_t)r * DMAX) + slot, z);
    }

    // ---- mel_len output + tail zeroing ----
    if (dg == 0) {
        if (tid == 0 && out_size >= MAIN + BATCH)
            out[MAIN + b] = (float)mel;
        if (b == 0) {
            for (int p = MAIN + BATCH + tid; p < out_size; p += 256)
                out[p] = 0.0f;
        }
    }
}

extern "C" void kernel_launch(void* const* d_in, const int* in_sizes, int n_in,
                              void* d_out, int out_size)
{
    const float* x   = (const float*)d_in[0];   // (16, 384, 512) f32
    const int*   dur = (const int*)d_in[1];     // (16, 512) i32
    float*       out = (float*)d_out;

    length_regulator_kernel<<<dim3(DIMSZ / ROWS, BATCH), 256>>>(x, dur, out, out_size);
}